// round 16
// baseline (speedup 1.0000x reference)
#include <cuda_runtime.h>
#include <math.h>

// ---------------------------------------------------------------------------
// StructureModule (Invariant Point Attention)
// B=1 N=768 C_S=384 C_Z=128 C_H=16 H=12 PQ=4 PV=8
// ---------------------------------------------------------------------------

#define NN    768
#define HH    12
#define CH    16
#define CZ    128
#define CS    384
#define PQn   4
#define PVn   8
#define INFV  100000.0f

// scales
#define S1   0.14433756729740643f   // sqrt(1/48)
#define S2   0.5773502691896258f    // sqrt(1/3)
#define SPT  0.13608276348795434f   // sqrt(1/54)

// ------------------------- device scratch ----------------------------------
__device__ float g_proj[NN * 1152];          // [n][1152]: q(192)|kv(384)|qp(144)|kvp(432)
__device__ float g_Eq[HH * NN * 32];         // [h][n][32]
__device__ float g_Ek[HH * NN * 32];         // [h][n][32]
__device__ float g_Vcat[HH * NN * 40];       // [h][n][40]: v(16) | v_pts global (24)
__device__ float g_a[HH * NN * NN];          // [h][q][k]  logits -> softmax probs
__device__ float g_cat[NN * 2112];           // [n][2112]

// ===========================================================================
// K1: projections  g_proj = s @ [Wq|Wkv|Wqp|Wkvp] + bias
// BM=64 BN=48 BK=16, 256 threads, grid (24, 12)
// ===========================================================================
__global__ __launch_bounds__(256) void proj_kernel(
    const float* __restrict__ s,
    const float* __restrict__ Wq,  const float* __restrict__ bq,
    const float* __restrict__ Wkv, const float* __restrict__ bkv,
    const float* __restrict__ Wqp, const float* __restrict__ bqp,
    const float* __restrict__ Wkvp,const float* __restrict__ bkvp)
{
    __shared__ float As[16][65];   // [kk][m]
    __shared__ float Ws[16][48];   // [kk][n]

    int n0 = blockIdx.x * 48;
    int m0 = blockIdx.y * 64;
    int tid = threadIdx.x;

    const float* W; const float* bias; int Nw, cl;
    if (n0 < 192)      { W = Wq;   bias = bq;   Nw = 192; cl = n0; }
    else if (n0 < 576) { W = Wkv;  bias = bkv;  Nw = 384; cl = n0 - 192; }
    else if (n0 < 720) { W = Wqp;  bias = bqp;  Nw = 144; cl = n0 - 576; }
    else               { W = Wkvp; bias = bkvp; Nw = 432; cl = n0 - 720; }

    int ty = tid >> 3;   // 0..31 -> m pair
    int tx = tid & 7;    // 0..7  -> 6 cols each

    float acc0[6] = {0,0,0,0,0,0};
    float acc1[6] = {0,0,0,0,0,0};

    for (int k0 = 0; k0 < CS; k0 += 16) {
        {   // A tile 64x16 transposed
            int r = tid >> 2, f = tid & 3;
            float4 v = *(const float4*)(s + (m0 + r) * CS + k0 + f * 4);
            As[f*4+0][r] = v.x; As[f*4+1][r] = v.y;
            As[f*4+2][r] = v.z; As[f*4+3][r] = v.w;
        }
        if (tid < 192) {  // W tile 16x48
            int r = tid / 12, f = tid % 12;
            float4 v = *(const float4*)(W + (k0 + r) * Nw + cl + f * 4);
            *(float4*)&Ws[r][f*4] = v;
        }
        __syncthreads();
#pragma unroll
        for (int kk = 0; kk < 16; kk++) {
            float a0 = As[kk][ty*2], a1 = As[kk][ty*2+1];
#pragma unroll
            for (int j = 0; j < 6; j++) {
                float w = Ws[kk][tx*6+j];
                acc0[j] += a0 * w;
                acc1[j] += a1 * w;
            }
        }
        __syncthreads();
    }
#pragma unroll
    for (int j = 0; j < 6; j++) {
        int c = tx*6 + j;
        float bv = bias[cl + c];
        g_proj[(m0 + ty*2    ) * 1152 + n0 + c] = acc0[j] + bv;
        g_proj[(m0 + ty*2 + 1) * 1152 + n0 + c] = acc1[j] + bv;
    }
}

// ===========================================================================
// K2: pack Eq/Ek/Vcat (rigid apply, scales, S-terms, mask terms)
// grid 768, block 192
// ===========================================================================
__global__ __launch_bounds__(192) void pack_kernel(
    const float* __restrict__ R, const float* __restrict__ t,
    const float* __restrict__ mask, const float* __restrict__ head_weights)
{
    int n = blockIdx.x;
    int tid = threadIdx.x;

    __shared__ float hw_s[12];
    __shared__ float sqv[48];   // |q_pt|^2 per point m
    __shared__ float skv[48];   // |k_pt|^2 per (h*4+p)

    if (tid < 12) {
        float x = head_weights[tid];
        float sp = (x > 20.f) ? x : log1pf(__expf(x));
        hw_s[tid] = sp * SPT;
    }
    __syncthreads();

    float r0 = R[n*9+0], r1 = R[n*9+1], r2 = R[n*9+2];
    float r3 = R[n*9+3], r4 = R[n*9+4], r5 = R[n*9+5];
    float r6 = R[n*9+6], r7 = R[n*9+7], r8 = R[n*9+8];
    float t0 = t[n*3+0], t1 = t[n*3+1], t2 = t[n*3+2];

    if (tid < 48) {
        int m = tid, h = m >> 2, p = m & 3;
        float x  = g_proj[n*1152 + 576       + m];
        float y  = g_proj[n*1152 + 576 + 48  + m];
        float zz = g_proj[n*1152 + 576 + 96  + m];
        float g0 = r0*x + r1*y + r2*zz + t0;
        float g1 = r3*x + r4*y + r5*zz + t1;
        float g2 = r6*x + r7*y + r8*zz + t2;
        float hw = hw_s[h];
        float* dst = &g_Eq[(h*NN + n)*32 + 16 + p*3];
        dst[0] = hw*g0; dst[1] = hw*g1; dst[2] = hw*g2;
        sqv[m] = g0*g0 + g1*g1 + g2*g2;
    } else {
        int m = tid - 48, h = m / 12, p = m % 12;
        float x  = g_proj[n*1152 + 720        + m];
        float y  = g_proj[n*1152 + 720 + 144  + m];
        float zz = g_proj[n*1152 + 720 + 288  + m];
        float g0 = r0*x + r1*y + r2*zz + t0;
        float g1 = r3*x + r4*y + r5*zz + t1;
        float g2 = r6*x + r7*y + r8*zz + t2;
        if (p < 4) {
            float* dst = &g_Ek[(h*NN + n)*32 + 16 + p*3];
            dst[0] = g0; dst[1] = g1; dst[2] = g2;
            skv[h*4 + p] = g0*g0 + g1*g1 + g2*g2;
        } else {
            float* dst = &g_Vcat[(h*NN + n)*40 + 16 + (p-4)*3];
            dst[0] = g0; dst[1] = g1; dst[2] = g2;
        }
    }

    // q / k / v channel copies (192 values each)
    {
        int h = tid >> 4, c = tid & 15;
        g_Eq[(h*NN + n)*32 + c]  = S1 * g_proj[n*1152 + h*16 + c];
        g_Ek[(h*NN + n)*32 + c]  = g_proj[n*1152 + 192 + h*32 + c];
        g_Vcat[(h*NN + n)*40 + c] = g_proj[n*1152 + 192 + h*32 + 16 + c];
    }
    __syncthreads();

    if (tid < 12) {
        int h = tid;
        float sq = sqv[h*4+0] + sqv[h*4+1] + sqv[h*4+2] + sqv[h*4+3];
        float sk = skv[h*4+0] + skv[h*4+1] + skv[h*4+2] + skv[h*4+3];
        float mq = mask[n];
        float* eq = &g_Eq[(h*NN + n)*32];
        float* ek = &g_Ek[(h*NN + n)*32];
        eq[28] = -0.5f * hw_s[h] * sq;  eq[29] = 1.f;
        eq[30] = INFV * mq;             eq[31] = 1.f;
        ek[28] = 1.f;                   ek[29] = -0.5f * hw_s[h] * sk;
        ek[30] = mq;                    ek[31] = -INFV;
    }
}

// ===========================================================================
// K3: z-pass 1:  g_a[h][q][k] = S2 * (z[q,k,:] @ Wb[:,h] + bb[h])
// grid (12 ktiles, 768 q), block 256
// ===========================================================================
__global__ __launch_bounds__(256) void bias_z_kernel(
    const float* __restrict__ z, const float* __restrict__ Wb,
    const float* __restrict__ bb)
{
    __shared__ float zs[64][132];
    __shared__ float wbT[12][132];

    int q  = blockIdx.y;
    int k0 = blockIdx.x * 64;
    int tid = threadIdx.x;

    for (int idx = tid; idx < 12*128; idx += 256) {
        int h = idx >> 7, c = idx & 127;
        wbT[h][c] = Wb[c*12 + h];
    }
    const float* zrow = z + ((size_t)(q * NN + k0)) * CZ;
#pragma unroll
    for (int j = 0; j < 8; j++) {
        int idx = tid + j*256;
        int r = idx >> 5, f = idx & 31;
        float4 v = *(const float4*)(zrow + r*CZ + f*4);
        *(float4*)&zs[r][f*4] = v;
    }
    __syncthreads();

    int kl = tid >> 2, grp = tid & 3;
    int h0 = grp * 3;
    float a0 = bb[h0], a1 = bb[h0+1], a2 = bb[h0+2];
#pragma unroll
    for (int c4 = 0; c4 < 32; c4++) {
        float4 zv = *(float4*)&zs[kl][c4*4];
        float4 w0 = *(float4*)&wbT[h0  ][c4*4];
        float4 w1 = *(float4*)&wbT[h0+1][c4*4];
        float4 w2 = *(float4*)&wbT[h0+2][c4*4];
        a0 += zv.x*w0.x + zv.y*w0.y + zv.z*w0.z + zv.w*w0.w;
        a1 += zv.x*w1.x + zv.y*w1.y + zv.z*w1.z + zv.w*w1.w;
        a2 += zv.x*w2.x + zv.y*w2.y + zv.z*w2.z + zv.w*w2.w;
    }
    int k = k0 + kl;
    g_a[((h0  )*NN + q)*NN + k] = S2 * a0;
    g_a[((h0+1)*NN + q)*NN + k] = S2 * a1;
    g_a[((h0+2)*NN + q)*NN + k] = S2 * a2;
}

// ===========================================================================
// K4: logits add:  g_a[h][q][k] += dot(Eq[h][q], Ek[h][k])   (32-dim)
// grid (24 kt, 24 qt, 12 h), block 256
// ===========================================================================
__global__ __launch_bounds__(256) void logits_kernel()
{
    __shared__ float Eqs[32][33];   // [c][q]
    __shared__ float Eks[32][36];   // [c][k]

    int h  = blockIdx.z;
    int q0 = blockIdx.y * 32;
    int k0 = blockIdx.x * 32;
    int tid = threadIdx.x;

    {
        int r = tid >> 3, f = tid & 7;
        float4 v = *(const float4*)&g_Eq[(h*NN + q0 + r)*32 + f*4];
        Eqs[f*4+0][r] = v.x; Eqs[f*4+1][r] = v.y;
        Eqs[f*4+2][r] = v.z; Eqs[f*4+3][r] = v.w;
        float4 w = *(const float4*)&g_Ek[(h*NN + k0 + r)*32 + f*4];
        Eks[f*4+0][r] = w.x; Eks[f*4+1][r] = w.y;
        Eks[f*4+2][r] = w.z; Eks[f*4+3][r] = w.w;
    }
    __syncthreads();

    int ty = tid >> 3;    // q row 0..31
    int tx = tid & 7;     // k group of 4
    float4 acc = make_float4(0.f, 0.f, 0.f, 0.f);
#pragma unroll
    for (int c = 0; c < 32; c++) {
        float aq = Eqs[c][ty];
        float4 bk = *(float4*)&Eks[c][tx*4];
        acc.x += aq * bk.x; acc.y += aq * bk.y;
        acc.z += aq * bk.z; acc.w += aq * bk.w;
    }
    float* ap = &g_a[(h*NN + q0 + ty)*NN + k0 + tx*4];
    float4 prev = *(float4*)ap;
    prev.x += acc.x; prev.y += acc.y; prev.z += acc.z; prev.w += acc.w;
    *(float4*)ap = prev;
}

// ===========================================================================
// K5: softmax over k, in place.  grid 9216 (h*768+q), block 256
// ===========================================================================
__global__ __launch_bounds__(256) void softmax_kernel()
{
    int row = blockIdx.x;
    float* a = &g_a[(size_t)row * NN];
    int tid = threadIdx.x;

    float v0 = a[tid], v1 = a[tid + 256], v2 = a[tid + 512];

    __shared__ float red[8];
    __shared__ float bcast;

    float m = fmaxf(fmaxf(v0, v1), v2);
#pragma unroll
    for (int o = 16; o; o >>= 1) m = fmaxf(m, __shfl_xor_sync(0xffffffffu, m, o));
    if ((tid & 31) == 0) red[tid >> 5] = m;
    __syncthreads();
    if (tid == 0) {
        float mm = red[0];
#pragma unroll
        for (int i = 1; i < 8; i++) mm = fmaxf(mm, red[i]);
        bcast = mm;
    }
    __syncthreads();
    m = bcast;

    float e0 = __expf(v0 - m), e1 = __expf(v1 - m), e2 = __expf(v2 - m);
    float s = e0 + e1 + e2;
#pragma unroll
    for (int o = 16; o; o >>= 1) s += __shfl_xor_sync(0xffffffffu, s, o);
    if ((tid & 31) == 0) red[tid >> 5] = s;
    __syncthreads();
    if (tid == 0) {
        float ss = red[0];
#pragma unroll
        for (int i = 1; i < 8; i++) ss += red[i];
        bcast = 1.f / ss;
    }
    __syncthreads();
    float inv = bcast;

    a[tid]       = e0 * inv;
    a[tid + 256] = e1 * inv;
    a[tid + 512] = e2 * inv;
}

// ===========================================================================
// K6: o and o_pt:  per head, O = A_h @ Vcat_h (768x768 @ 768x40),
//     then point transform to local frame + norms, write into g_cat
// grid (12 qtiles, 12 h), block 256
// ===========================================================================
__global__ __launch_bounds__(256) void ov_kernel(
    const float* __restrict__ R, const float* __restrict__ t)
{
    __shared__ float As[64][68];
    __shared__ float Vcs[64][44];

    int h  = blockIdx.y;
    int q0 = blockIdx.x * 64;
    int tid = threadIdx.x;
    int ql = tid >> 2, cg = tid & 3;     // 64 rows x 4 col-groups (10 cols each)

    float acc[10];
#pragma unroll
    for (int j = 0; j < 10; j++) acc[j] = 0.f;

    for (int k0 = 0; k0 < NN; k0 += 64) {
#pragma unroll
        for (int j = 0; j < 4; j++) {
            int idx = tid + j*256;
            int r = idx >> 4, f = idx & 15;
            float4 v = *(const float4*)&g_a[(h*NN + q0 + r)*NN + k0 + f*4];
            *(float4*)&As[r][f*4] = v;
        }
#pragma unroll
        for (int j = 0; j < 3; j++) {
            int idx = tid + j*256;
            if (idx < 640) {
                int r = idx / 10, f = idx % 10;
                float4 v = *(const float4*)&g_Vcat[(h*NN + k0 + r)*40 + f*4];
                *(float4*)&Vcs[r][f*4] = v;
            }
        }
        __syncthreads();
#pragma unroll 8
        for (int kk = 0; kk < 64; kk++) {
            float av = As[ql][kk];
#pragma unroll
            for (int j = 0; j < 5; j++) {
                float2 vv = *(float2*)&Vcs[kk][cg*10 + j*2];
                acc[2*j]   += av * vv.x;
                acc[2*j+1] += av * vv.y;
            }
        }
        __syncthreads();
    }

    // stage block outputs (reuse As as Os[64][40], stride 68)
#pragma unroll
    for (int j = 0; j < 10; j++) As[ql][cg*10 + j] = acc[j];
    __syncthreads();

    // o channels -> cat[:, h*16+c]
    for (int idx = tid; idx < 1024; idx += 256) {
        int r = idx >> 4, c = idx & 15;
        g_cat[(q0 + r)*2112 + h*16 + c] = As[r][c];
    }
    // points: local transform + norm
    for (int idx = tid; idx < 512; idx += 256) {
        int r = idx >> 3, p = idx & 7;
        int q = q0 + r;
        float d0 = As[r][16 + p*3 + 0] - t[q*3+0];
        float d1 = As[r][16 + p*3 + 1] - t[q*3+1];
        float d2 = As[r][16 + p*3 + 2] - t[q*3+2];
        float l0 = R[q*9+0]*d0 + R[q*9+3]*d1 + R[q*9+6]*d2;
        float l1 = R[q*9+1]*d0 + R[q*9+4]*d1 + R[q*9+7]*d2;
        float l2 = R[q*9+2]*d0 + R[q*9+5]*d1 + R[q*9+8]*d2;
        float nr = sqrtf(l0*l0 + l1*l1 + l2*l2 + 1e-8f);
        int hp = h*8 + p;
        float* cr = &g_cat[(size_t)q * 2112];
        cr[192 + hp] = l0;
        cr[288 + hp] = l1;
        cr[384 + hp] = l2;
        cr[480 + hp] = nr;
    }
}

// ===========================================================================
// K7: z-pass 2 (o_pair):  cat[q, 576 + h*128 + zc] = sum_k a[h][q][k] * z[q,k,zc]
// grid 768 (q), block 256: thread = (zc 0..127, hgroup 0..1 of 6 heads)
// ===========================================================================
__global__ __launch_bounds__(256) void opair_kernel(const float* __restrict__ z)
{
    __shared__ float as_s[12][256];

    int q = blockIdx.x;
    int tid = threadIdx.x;
    int zc = tid & 127;
    int h0 = (tid >> 7) * 6;

    float acc[6];
#pragma unroll
    for (int e = 0; e < 6; e++) acc[e] = 0.f;

    for (int kc = 0; kc < NN; kc += 256) {
        __syncthreads();
#pragma unroll
        for (int j = 0; j < 3; j++) {
            int idx = tid + j*256;
            int hh = idx >> 6, f = idx & 63;
            *(float4*)&as_s[hh][f*4] =
                *(const float4*)&g_a[(hh*NN + q)*NN + kc + f*4];
        }
        __syncthreads();
        const float* zp = z + ((size_t)(q*NN + kc)) * CZ + zc;
#pragma unroll 4
        for (int k4 = 0; k4 < 64; k4++) {
            float z0 = zp[(k4*4 + 0) * CZ];
            float z1 = zp[(k4*4 + 1) * CZ];
            float z2 = zp[(k4*4 + 2) * CZ];
            float z3 = zp[(k4*4 + 3) * CZ];
#pragma unroll
            for (int e = 0; e < 6; e++) {
                float4 av = *(float4*)&as_s[h0 + e][k4*4];
                acc[e] += av.x*z0 + av.y*z1 + av.z*z2 + av.w*z3;
            }
        }
    }
    float* cr = &g_cat[(size_t)q * 2112 + 576];
#pragma unroll
    for (int e = 0; e < 6; e++)
        cr[(h0 + e) * 128 + zc] = acc[e];
}

// ===========================================================================
// K8: output GEMM:  out = cat[768,2112] @ Wout[2112,384] + bout
// BM=32 BN=64 BK=16, 256 threads, grid (6, 24)
// ===========================================================================
__global__ __launch_bounds__(256) void out_gemm_kernel(
    const float* __restrict__ Wout, const float* __restrict__ bout,
    float* __restrict__ out)
{
    __shared__ float As[16][36];   // [kk][m]
    __shared__ float Ws[16][68];   // [kk][n]

    int m0 = blockIdx.y * 32;
    int n0 = blockIdx.x * 64;
    int tid = threadIdx.x;
    int ty = tid >> 4;   // 0..15 -> m pair
    int tx = tid & 15;   // 0..15 -> 4 cols

    float acc0[4] = {0,0,0,0};
    float acc1[4] = {0,0,0,0};

    for (int k0 = 0; k0 < 2112; k0 += 16) {
        if (tid < 128) {
            int r = tid >> 2, f = tid & 3;
            float4 v = *(const float4*)&g_cat[(m0 + r)*2112 + k0 + f*4];
            As[f*4+0][r] = v.x; As[f*4+1][r] = v.y;
            As[f*4+2][r] = v.z; As[f*4+3][r] = v.w;
        }
        {
            int r = tid >> 4, f = tid & 15;
            float4 v = *(const float4*)(Wout + (k0 + r)*384 + n0 + f*4);
            *(float4*)&Ws[r][f*4] = v;
        }
        __syncthreads();
#pragma unroll
        for (int kk = 0; kk < 16; kk++) {
            float a0 = As[kk][ty*2], a1 = As[kk][ty*2+1];
            float4 w = *(float4*)&Ws[kk][tx*4];
            acc0[0] += a0*w.x; acc0[1] += a0*w.y; acc0[2] += a0*w.z; acc0[3] += a0*w.w;
            acc1[0] += a1*w.x; acc1[1] += a1*w.y; acc1[2] += a1*w.z; acc1[3] += a1*w.w;
        }
        __syncthreads();
    }
    float4 b4 = *(const float4*)(bout + n0 + tx*4);
    {
        float4 o;
        o.x = acc0[0] + b4.x; o.y = acc0[1] + b4.y;
        o.z = acc0[2] + b4.z; o.w = acc0[3] + b4.w;
        *(float4*)&out[(m0 + ty*2) * 384 + n0 + tx*4] = o;
    }
    {
        float4 o;
        o.x = acc1[0] + b4.x; o.y = acc1[1] + b4.y;
        o.z = acc1[2] + b4.z; o.w = acc1[3] + b4.w;
        *(float4*)&out[(m0 + ty*2 + 1) * 384 + n0 + tx*4] = o;
    }
}

// ===========================================================================
// launch
// ===========================================================================
extern "C" void kernel_launch(void* const* d_in, const int* in_sizes, int n_in,
                              void* d_out, int out_size)
{
    const float* s    = (const float*)d_in[0];
    const float* z    = (const float*)d_in[1];
    const float* R    = (const float*)d_in[2];
    const float* t    = (const float*)d_in[3];
    const float* mask = (const float*)d_in[4];
    const float* Wq   = (const float*)d_in[5];
    const float* bq   = (const float*)d_in[6];
    const float* Wkv  = (const float*)d_in[7];
    const float* bkv  = (const float*)d_in[8];
    const float* Wqp  = (const float*)d_in[9];
    const float* bqp  = (const float*)d_in[10];
    const float* Wkvp = (const float*)d_in[11];
    const float* bkvp = (const float*)d_in[12];
    const float* Wb   = (const float*)d_in[13];
    const float* bb   = (const float*)d_in[14];
    const float* hwts = (const float*)d_in[15];
    const float* Wout = (const float*)d_in[16];
    const float* bout = (const float*)d_in[17];
    float* out = (float*)d_out;

    proj_kernel<<<dim3(24, 12), 256>>>(s, Wq, bq, Wkv, bkv, Wqp, bqp, Wkvp, bkvp);
    pack_kernel<<<768, 192>>>(R, t, mask, hwts);
    bias_z_kernel<<<dim3(12, 768), 256>>>(z, Wb, bb);
    logits_kernel<<<dim3(24, 24, 12), 256>>>();
    softmax_kernel<<<9216, 256>>>();
    ov_kernel<<<dim3(12, 12), 256>>>(R, t);
    opair_kernel<<<768, 256>>>(z);
    out_gemm_kernel<<<dim3(6, 24), 256>>>(Wout, bout, out);
}